// round 7
// baseline (speedup 1.0000x reference)
#include <cuda_runtime.h>
#include <math.h>

// Shapes (fixed by the problem)
#define BB   128
#define NN   32
#define MM   64
#define OBS_ 128
#define ACT_ 16
#define DQK_ 128
#define DAV_ 64
#define HID_ 64

// Output offsets: value [B,N,N,1] | weight [B,N,N] | weight_other [B,N,M]
#define OFF_VAL 0
#define OFF_W   (BB * NN * NN)            // 131072
#define OFF_WO  (2 * BB * NN * NN)        // 262144

// Padded shared-memory workspace. Row strides 129 / 65 / 33 are odd -> any
// fixed-column access across lanes hits 32 distinct banks.
struct Smem {
    float s[32][129];        // states[b]               (alive whole kernel)
    float ka[64][129];       // key_obs (rows 0..31) -> later states_other
    float kb[64][129];       // query_obs (rows 0..31) -> later keys_other
    float qa[32][129];       // query_agent
    float w[32][33];         // logits -> softmax weight
    float av_act[32][65];
    float delta[32][65];     // tanh(av_pol) - tanh(av_act)
    float base_[32][65];     // weight @ av_act
    float w_o[32][65];       // logits_other -> softmax weight_other
    float av_o[64][65];
    float wav_o[32][65];
    float u[32][65];
    float v[32][65];
    float act[32][16];
    float pol[32][16];
    float act_o[64][16];
    float wf2[64];
};

__device__ __forceinline__ float warp_max(float x) {
    #pragma unroll
    for (int off = 16; off; off >>= 1)
        x = fmaxf(x, __shfl_xor_sync(0xffffffffu, x, off));
    return x;
}
__device__ __forceinline__ float warp_sum(float x) {
    #pragma unroll
    for (int off = 16; off; off >>= 1)
        x += __shfl_xor_sync(0xffffffffu, x, off);
    return x;
}

__global__ __launch_bounds__(256, 1)
void critic_dual_attn_kernel(const float* __restrict__ states,
                             const float* __restrict__ policies,
                             const float* __restrict__ actions,
                             const float* __restrict__ states_other,
                             const float* __restrict__ actions_other,
                             const float* __restrict__ W_key,
                             const float* __restrict__ W_query,
                             const float* __restrict__ W_av,
                             const float* __restrict__ W_key_other,
                             const float* __restrict__ W_query_other,
                             const float* __restrict__ W_av_other,
                             const float* __restrict__ W_f1,
                             const float* __restrict__ W_f2,
                             float* __restrict__ out)
{
    extern __shared__ char smem_raw[];
    Smem& sm = *reinterpret_cast<Smem*>(smem_raw);

    const int b    = blockIdx.x;
    const int tid  = threadIdx.x;
    const int lane = tid & 31;
    const int warp = tid >> 5;
    const float scale = 0.08838834764831845f;   // 1/sqrt(128)

    // ---------------- Phase A: load per-batch agent inputs ----------------
    for (int idx = tid; idx < NN * OBS_; idx += 256)
        sm.s[idx >> 7][idx & 127] = states[b * NN * OBS_ + idx];
    for (int idx = tid; idx < NN * ACT_; idx += 256) {
        sm.act[idx >> 4][idx & 15] = actions[b * NN * ACT_ + idx];
        sm.pol[idx >> 4][idx & 15] = policies[b * NN * ACT_ + idx];
    }
    for (int idx = tid; idx < MM * ACT_; idx += 256)
        sm.act_o[idx >> 4][idx & 15] = actions_other[b * MM * ACT_ + idx];
    if (tid < 64) sm.wf2[tid] = W_f2[tid];
    __syncthreads();

    // ---------------- Phase B: key_obs & query_obs  [32,128] ----------------
    {
        const int o  = tid & 127;
        const int ih = tid >> 7;              // 0/1 -> 16 rows each
        float aK[16], aQ[16];
        #pragma unroll
        for (int r = 0; r < 16; r++) { aK[r] = 0.f; aQ[r] = 0.f; }
        for (int k = 0; k < OBS_; k++) {
            float wk = W_key[k * DQK_ + o];
            float wq = W_query[k * DQK_ + o];
            #pragma unroll
            for (int r = 0; r < 16; r++) {
                float sv = sm.s[ih * 16 + r][k];
                aK[r] = fmaf(sv, wk, aK[r]);
                aQ[r] = fmaf(sv, wq, aQ[r]);
            }
        }
        #pragma unroll
        for (int r = 0; r < 16; r++) {
            sm.ka[ih * 16 + r][o] = aK[r];
            sm.kb[ih * 16 + r][o] = aQ[r];
        }
    }
    __syncthreads();

    // ---------------- Phase C: logits = q @ k^T * scale  [32,32] ----------------
    for (int idx = tid; idx < NN * NN; idx += 256) {
        int i = idx >> 5, j = idx & 31;
        float acc = 0.f;
        #pragma unroll 4
        for (int d = 0; d < DQK_; d++)
            acc = fmaf(sm.kb[i][d], sm.ka[j][d], acc);
        sm.w[i][j] = acc * scale;
    }
    __syncthreads();

    // softmax rows of w, emit ret_weight
    for (int r = warp; r < NN; r += 8) {
        float x  = sm.w[r][lane];
        float mx = warp_max(x);
        float e  = __expf(x - mx);
        float sv = warp_sum(e);
        float o  = e / sv;
        sm.w[r][lane] = o;
        out[OFF_W + b * NN * NN + r * NN + lane] = o;
    }
    __syncthreads();

    // ---------------- Phase D: states_other load, av_act/delta, query_agent ----------------
    for (int idx = tid; idx < MM * OBS_; idx += 256)
        sm.ka[idx >> 7][idx & 127] = states_other[b * MM * OBS_ + idx];

    {   // av_act / av_pol -> delta  (share the 128-wide states part)
        const int o = tid & 63;
        const int g = tid >> 6;               // 0..3 -> 8 rows each
        float aS[8];
        #pragma unroll
        for (int r = 0; r < 8; r++) aS[r] = 0.f;
        for (int k = 0; k < OBS_; k++) {
            float wv = W_av[k * DAV_ + o];
            #pragma unroll
            for (int r = 0; r < 8; r++)
                aS[r] = fmaf(sm.s[g * 8 + r][k], wv, aS[r]);
        }
        float aA[8], aP[8];
        #pragma unroll
        for (int r = 0; r < 8; r++) { aA[r] = aS[r]; aP[r] = aS[r]; }
        #pragma unroll
        for (int k = 0; k < ACT_; k++) {
            float wv = W_av[(OBS_ + k) * DAV_ + o];
            #pragma unroll
            for (int r = 0; r < 8; r++) {
                aA[r] = fmaf(sm.act[g * 8 + r][k], wv, aA[r]);
                aP[r] = fmaf(sm.pol[g * 8 + r][k], wv, aP[r]);
            }
        }
        #pragma unroll
        for (int r = 0; r < 8; r++) {
            float ta = tanhf(aA[r]);
            sm.av_act[g * 8 + r][o] = ta;
            sm.delta[g * 8 + r][o]  = tanhf(aP[r]) - ta;
        }
    }

    {   // query_agent = states @ W_query_other  [32,128]
        const int o  = tid & 127;
        const int ih = tid >> 7;
        float a[16];
        #pragma unroll
        for (int r = 0; r < 16; r++) a[r] = 0.f;
        for (int k = 0; k < OBS_; k++) {
            float wv = W_query_other[k * DQK_ + o];
            #pragma unroll
            for (int r = 0; r < 16; r++)
                a[r] = fmaf(sm.s[ih * 16 + r][k], wv, a[r]);
        }
        #pragma unroll
        for (int r = 0; r < 16; r++) sm.qa[ih * 16 + r][o] = a[r];
    }
    __syncthreads();

    // ---------------- Phase E: keys_other [64,128], base = w @ av_act ----------------
    {
        const int o  = tid & 127;
        const int ih = tid >> 7;              // 0/1 -> 32 rows each
        float a[32];
        #pragma unroll
        for (int r = 0; r < 32; r++) a[r] = 0.f;
        #pragma unroll 1
        for (int k = 0; k < OBS_; k++) {
            float wv = W_key_other[k * DQK_ + o];
            #pragma unroll
            for (int r = 0; r < 32; r++)
                a[r] = fmaf(sm.ka[ih * 32 + r][k], wv, a[r]);
        }
        #pragma unroll
        for (int r = 0; r < 32; r++) sm.kb[ih * 32 + r][o] = a[r];
    }
    {
        const int o = tid & 63;
        const int g = tid >> 6;
        float a[8];
        #pragma unroll
        for (int r = 0; r < 8; r++) a[r] = 0.f;
        #pragma unroll 4
        for (int k = 0; k < NN; k++) {
            float av = sm.av_act[k][o];
            #pragma unroll
            for (int r = 0; r < 8; r++)
                a[r] = fmaf(sm.w[g * 8 + r][k], av, a[r]);
        }
        #pragma unroll
        for (int r = 0; r < 8; r++) sm.base_[g * 8 + r][o] = a[r];
    }
    __syncthreads();

    // ---------------- Phase F: logits_other [32,64] ----------------
    for (int idx = tid; idx < NN * MM; idx += 256) {
        int i = idx >> 6, m = idx & 63;
        float acc = 0.f;
        #pragma unroll 4
        for (int d = 0; d < DQK_; d++)
            acc = fmaf(sm.qa[i][d], sm.kb[m][d], acc);
        sm.w_o[i][m] = acc * scale;
    }
    __syncthreads();

    // softmax weight_other (row length 64: 2 per lane), emit; plus av_other
    for (int r = warp; r < NN; r += 8) {
        float x0 = sm.w_o[r][lane];
        float x1 = sm.w_o[r][lane + 32];
        float mx = warp_max(fmaxf(x0, x1));
        float e0 = __expf(x0 - mx), e1 = __expf(x1 - mx);
        float sv = warp_sum(e0 + e1);
        float o0 = e0 / sv, o1 = e1 / sv;
        sm.w_o[r][lane]      = o0;
        sm.w_o[r][lane + 32] = o1;
        out[OFF_WO + b * NN * MM + r * MM + lane]      = o0;
        out[OFF_WO + b * NN * MM + r * MM + lane + 32] = o1;
    }
    {   // av_other = tanh(concat(states_other, actions_other) @ W_av_other)  [64,64]
        const int o = tid & 63;
        const int g = tid >> 6;               // 0..3 -> 16 rows each
        float a[16];
        #pragma unroll
        for (int r = 0; r < 16; r++) a[r] = 0.f;
        #pragma unroll 1
        for (int k = 0; k < OBS_; k++) {
            float wv = W_av_other[k * DAV_ + o];
            #pragma unroll
            for (int r = 0; r < 16; r++)
                a[r] = fmaf(sm.ka[g * 16 + r][k], wv, a[r]);
        }
        #pragma unroll
        for (int k = 0; k < ACT_; k++) {
            float wv = W_av_other[(OBS_ + k) * DAV_ + o];
            #pragma unroll
            for (int r = 0; r < 16; r++)
                a[r] = fmaf(sm.act_o[g * 16 + r][k], wv, a[r]);
        }
        #pragma unroll
        for (int r = 0; r < 16; r++) sm.av_o[g * 16 + r][o] = tanhf(a[r]);
    }
    __syncthreads();

    // ---------------- Phase G: wav_other = weight_other @ av_other  [32,64] ----------------
    {
        const int o = tid & 63;
        const int g = tid >> 6;
        float a[8];
        #pragma unroll
        for (int r = 0; r < 8; r++) a[r] = 0.f;
        #pragma unroll 2
        for (int m = 0; m < MM; m++) {
            float av = sm.av_o[m][o];
            #pragma unroll
            for (int r = 0; r < 8; r++)
                a[r] = fmaf(sm.w_o[g * 8 + r][m], av, a[r]);
        }
        #pragma unroll
        for (int r = 0; r < 8; r++) sm.wav_o[g * 8 + r][o] = a[r];
    }
    __syncthreads();

    // ---------------- Phase H: u = [base|wav_o] @ W_f1,  v = delta @ W_f1[:64] ----------------
    {
        const int o = tid & 63;
        const int g = tid >> 6;
        float aU[8], aV[8];
        #pragma unroll
        for (int r = 0; r < 8; r++) { aU[r] = 0.f; aV[r] = 0.f; }
        #pragma unroll 2
        for (int k = 0; k < DAV_; k++) {
            float wf = W_f1[k * HID_ + o];
            #pragma unroll
            for (int r = 0; r < 8; r++) {
                aU[r] = fmaf(sm.base_[g * 8 + r][k], wf, aU[r]);
                aV[r] = fmaf(sm.delta[g * 8 + r][k], wf, aV[r]);
            }
        }
        #pragma unroll 2
        for (int k = 0; k < DAV_; k++) {
            float wf = W_f1[(DAV_ + k) * HID_ + o];
            #pragma unroll
            for (int r = 0; r < 8; r++)
                aU[r] = fmaf(sm.wav_o[g * 8 + r][k], wf, aU[r]);
        }
        #pragma unroll
        for (int r = 0; r < 8; r++) {
            sm.u[g * 8 + r][o] = aU[r];
            sm.v[g * 8 + r][o] = aV[r];
        }
    }
    __syncthreads();

    // ---------------- Phase I: value[i,j] = sum_f wf2[f]*lrelu(u[i,f] + w[i,j]*v[j,f]) ----------------
    for (int idx = tid; idx < NN * NN; idx += 256) {
        int i = idx >> 5, j = idx & 31;
        float wij = sm.w[i][j];
        float acc = 0.f;
        #pragma unroll 8
        for (int f = 0; f < HID_; f++) {
            float p = fmaf(wij, sm.v[j][f], sm.u[i][f]);
            float l = p > 0.f ? p : 0.01f * p;
            acc = fmaf(sm.wf2[f], l, acc);
        }
        out[OFF_VAL + b * NN * NN + i * NN + j] = acc;
    }
}

extern "C" void kernel_launch(void* const* d_in, const int* in_sizes, int n_in,
                              void* d_out, int out_size) {
    const float* states        = (const float*)d_in[0];
    const float* policies      = (const float*)d_in[1];
    const float* actions       = (const float*)d_in[2];
    const float* states_other  = (const float*)d_in[3];
    const float* actions_other = (const float*)d_in[4];
    const float* W_key         = (const float*)d_in[5];
    const float* W_query       = (const float*)d_in[6];
    const float* W_av          = (const float*)d_in[7];
    const float* W_key_other   = (const float*)d_in[8];
    const float* W_query_other = (const float*)d_in[9];
    const float* W_av_other    = (const float*)d_in[10];
    const float* W_f1          = (const float*)d_in[11];
    const float* W_f2          = (const float*)d_in[12];
    float* out = (float*)d_out;

    const int smem_bytes = (int)sizeof(Smem);   // ~182 KB
    cudaFuncSetAttribute(critic_dual_attn_kernel,
                         cudaFuncAttributeMaxDynamicSharedMemorySize, smem_bytes);

    critic_dual_attn_kernel<<<BB, 256, smem_bytes>>>(
        states, policies, actions, states_other, actions_other,
        W_key, W_query, W_av, W_key_other, W_query_other, W_av_other,
        W_f1, W_f2, out);
}

// round 8
// speedup vs baseline: 1.0020x; 1.0020x over previous
#include <cuda_runtime.h>
#include <math.h>

// Shapes (fixed by the problem)
#define BB   128
#define NN   32
#define MM   64
#define OBS_ 128
#define ACT_ 16
#define DQK_ 128
#define DAV_ 64
#define HID_ 64

// Output offsets: value [B,N,N,1] | weight [B,N,N] | weight_other [B,N,M]
#define OFF_VAL 0
#define OFF_W   (BB * NN * NN)            // 131072
#define OFF_WO  (2 * BB * NN * NN)        // 262144

// Padded shared-memory workspace. Row strides 129 / 65 / 33 are odd -> any
// fixed-column access across lanes hits 32 distinct banks.
struct Smem {
    float s[32][129];        // states[b]               (alive whole kernel)
    float ka[64][129];       // key_obs (rows 0..31) -> later states_other
    float kb[64][129];       // query_obs (rows 0..31) -> later keys_other
    float qa[32][129];       // query_agent
    float w[32][33];         // logits -> softmax weight
    float av_act[32][65];
    float delta[32][65];     // tanh(av_pol) - tanh(av_act)
    float base_[32][65];     // weight @ av_act
    float w_o[32][65];       // logits_other -> softmax weight_other
    float av_o[64][65];
    float wav_o[32][65];
    float u[32][65];
    float v[32][65];
    float act[32][16];
    float pol[32][16];
    float act_o[64][16];
    float wf2[64];
};

__device__ __forceinline__ float warp_max(float x) {
    #pragma unroll
    for (int off = 16; off; off >>= 1)
        x = fmaxf(x, __shfl_xor_sync(0xffffffffu, x, off));
    return x;
}
__device__ __forceinline__ float warp_sum(float x) {
    #pragma unroll
    for (int off = 16; off; off >>= 1)
        x += __shfl_xor_sync(0xffffffffu, x, off);
    return x;
}

__global__ __launch_bounds__(256, 1)
void critic_dual_attn_kernel(const float* __restrict__ states,
                             const float* __restrict__ policies,
                             const float* __restrict__ actions,
                             const float* __restrict__ states_other,
                             const float* __restrict__ actions_other,
                             const float* __restrict__ W_key,
                             const float* __restrict__ W_query,
                             const float* __restrict__ W_av,
                             const float* __restrict__ W_key_other,
                             const float* __restrict__ W_query_other,
                             const float* __restrict__ W_av_other,
                             const float* __restrict__ W_f1,
                             const float* __restrict__ W_f2,
                             float* __restrict__ out)
{
    extern __shared__ char smem_raw[];
    Smem& sm = *reinterpret_cast<Smem*>(smem_raw);

    const int b    = blockIdx.x;
    const int tid  = threadIdx.x;
    const int lane = tid & 31;
    const int warp = tid >> 5;
    const float scale = 0.08838834764831845f;   // 1/sqrt(128)

    // ---------------- Phase A: load per-batch agent inputs ----------------
    for (int idx = tid; idx < NN * OBS_; idx += 256)
        sm.s[idx >> 7][idx & 127] = states[b * NN * OBS_ + idx];
    for (int idx = tid; idx < NN * ACT_; idx += 256) {
        sm.act[idx >> 4][idx & 15] = actions[b * NN * ACT_ + idx];
        sm.pol[idx >> 4][idx & 15] = policies[b * NN * ACT_ + idx];
    }
    for (int idx = tid; idx < MM * ACT_; idx += 256)
        sm.act_o[idx >> 4][idx & 15] = actions_other[b * MM * ACT_ + idx];
    if (tid < 64) sm.wf2[tid] = W_f2[tid];
    __syncthreads();

    // ---------------- Phase B: key_obs & query_obs  [32,128] ----------------
    {
        const int o  = tid & 127;
        const int ih = tid >> 7;              // 0/1 -> 16 rows each
        float aK[16], aQ[16];
        #pragma unroll
        for (int r = 0; r < 16; r++) { aK[r] = 0.f; aQ[r] = 0.f; }
        for (int k = 0; k < OBS_; k++) {
            float wk = W_key[k * DQK_ + o];
            float wq = W_query[k * DQK_ + o];
            #pragma unroll
            for (int r = 0; r < 16; r++) {
                float sv = sm.s[ih * 16 + r][k];
                aK[r] = fmaf(sv, wk, aK[r]);
                aQ[r] = fmaf(sv, wq, aQ[r]);
            }
        }
        #pragma unroll
        for (int r = 0; r < 16; r++) {
            sm.ka[ih * 16 + r][o] = aK[r];
            sm.kb[ih * 16 + r][o] = aQ[r];
        }
    }
    __syncthreads();

    // ---------------- Phase C: logits = q @ k^T * scale  [32,32] ----------------
    for (int idx = tid; idx < NN * NN; idx += 256) {
        int i = idx >> 5, j = idx & 31;
        float acc = 0.f;
        #pragma unroll 4
        for (int d = 0; d < DQK_; d++)
            acc = fmaf(sm.kb[i][d], sm.ka[j][d], acc);
        sm.w[i][j] = acc * scale;
    }
    __syncthreads();

    // softmax rows of w, emit ret_weight
    for (int r = warp; r < NN; r += 8) {
        float x  = sm.w[r][lane];
        float mx = warp_max(x);
        float e  = __expf(x - mx);
        float sv = warp_sum(e);
        float o  = e / sv;
        sm.w[r][lane] = o;
        out[OFF_W + b * NN * NN + r * NN + lane] = o;
    }
    __syncthreads();

    // ---------------- Phase D: states_other load, av_act/delta, query_agent ----------------
    for (int idx = tid; idx < MM * OBS_; idx += 256)
        sm.ka[idx >> 7][idx & 127] = states_other[b * MM * OBS_ + idx];

    {   // av_act / av_pol -> delta  (share the 128-wide states part)
        const int o = tid & 63;
        const int g = tid >> 6;               // 0..3 -> 8 rows each
        float aS[8];
        #pragma unroll
        for (int r = 0; r < 8; r++) aS[r] = 0.f;
        for (int k = 0; k < OBS_; k++) {
            float wv = W_av[k * DAV_ + o];
            #pragma unroll
            for (int r = 0; r < 8; r++)
                aS[r] = fmaf(sm.s[g * 8 + r][k], wv, aS[r]);
        }
        float aA[8], aP[8];
        #pragma unroll
        for (int r = 0; r < 8; r++) { aA[r] = aS[r]; aP[r] = aS[r]; }
        #pragma unroll
        for (int k = 0; k < ACT_; k++) {
            float wv = W_av[(OBS_ + k) * DAV_ + o];
            #pragma unroll
            for (int r = 0; r < 8; r++) {
                aA[r] = fmaf(sm.act[g * 8 + r][k], wv, aA[r]);
                aP[r] = fmaf(sm.pol[g * 8 + r][k], wv, aP[r]);
            }
        }
        #pragma unroll
        for (int r = 0; r < 8; r++) {
            float ta = tanhf(aA[r]);
            sm.av_act[g * 8 + r][o] = ta;
            sm.delta[g * 8 + r][o]  = tanhf(aP[r]) - ta;
        }
    }

    {   // query_agent = states @ W_query_other  [32,128]
        const int o  = tid & 127;
        const int ih = tid >> 7;
        float a[16];
        #pragma unroll
        for (int r = 0; r < 16; r++) a[r] = 0.f;
        for (int k = 0; k < OBS_; k++) {
            float wv = W_query_other[k * DQK_ + o];
            #pragma unroll
            for (int r = 0; r < 16; r++)
                a[r] = fmaf(sm.s[ih * 16 + r][k], wv, a[r]);
        }
        #pragma unroll
        for (int r = 0; r < 16; r++) sm.qa[ih * 16 + r][o] = a[r];
    }
    __syncthreads();

    // ---------------- Phase E: keys_other [64,128], base = w @ av_act ----------------
    {
        const int o  = tid & 127;
        const int ih = tid >> 7;              // 0/1 -> 32 rows each
        float a[32];
        #pragma unroll
        for (int r = 0; r < 32; r++) a[r] = 0.f;
        #pragma unroll 1
        for (int k = 0; k < OBS_; k++) {
            float wv = W_key_other[k * DQK_ + o];
            #pragma unroll
            for (int r = 0; r < 32; r++)
                a[r] = fmaf(sm.ka[ih * 32 + r][k], wv, a[r]);
        }
        #pragma unroll
        for (int r = 0; r < 32; r++) sm.kb[ih * 32 + r][o] = a[r];
    }
    {
        const int o = tid & 63;
        const int g = tid >> 6;
        float a[8];
        #pragma unroll
        for (int r = 0; r < 8; r++) a[r] = 0.f;
        #pragma unroll 4
        for (int k = 0; k < NN; k++) {
            float av = sm.av_act[k][o];
            #pragma unroll
            for (int r = 0; r < 8; r++)
                a[r] = fmaf(sm.w[g * 8 + r][k], av, a[r]);
        }
        #pragma unroll
        for (int r = 0; r < 8; r++) sm.base_[g * 8 + r][o] = a[r];
    }
    __syncthreads();

    // ---------------- Phase F: logits_other [32,64] ----------------
    for (int idx = tid; idx < NN * MM; idx += 256) {
        int i = idx >> 6, m = idx & 63;
        float acc = 0.f;
        #pragma unroll 4
        for (int d = 0; d < DQK_; d++)
            acc = fmaf(sm.qa[i][d], sm.kb[m][d], acc);
        sm.w_o[i][m] = acc * scale;
    }
    __syncthreads();

    // softmax weight_other (row length 64: 2 per lane), emit; plus av_other
    for (int r = warp; r < NN; r += 8) {
        float x0 = sm.w_o[r][lane];
        float x1 = sm.w_o[r][lane + 32];
        float mx = warp_max(fmaxf(x0, x1));
        float e0 = __expf(x0 - mx), e1 = __expf(x1 - mx);
        float sv = warp_sum(e0 + e1);
        float o0 = e0 / sv, o1 = e1 / sv;
        sm.w_o[r][lane]      = o0;
        sm.w_o[r][lane + 32] = o1;
        out[OFF_WO + b * NN * MM + r * MM + lane]      = o0;
        out[OFF_WO + b * NN * MM + r * MM + lane + 32] = o1;
    }
    {   // av_other = tanh(concat(states_other, actions_other) @ W_av_other)  [64,64]
        const int o = tid & 63;
        const int g = tid >> 6;               // 0..3 -> 16 rows each
        float a[16];
        #pragma unroll
        for (int r = 0; r < 16; r++) a[r] = 0.f;
        #pragma unroll 1
        for (int k = 0; k < OBS_; k++) {
            float wv = W_av_other[k * DAV_ + o];
            #pragma unroll
            for (int r = 0; r < 16; r++)
                a[r] = fmaf(sm.ka[g * 16 + r][k], wv, a[r]);
        }
        #pragma unroll
        for (int k = 0; k < ACT_; k++) {
            float wv = W_av_other[(OBS_ + k) * DAV_ + o];
            #pragma unroll
            for (int r = 0; r < 16; r++)
                a[r] = fmaf(sm.act_o[g * 16 + r][k], wv, a[r]);
        }
        #pragma unroll
        for (int r = 0; r < 16; r++) sm.av_o[g * 16 + r][o] = tanhf(a[r]);
    }
    __syncthreads();

    // ---------------- Phase G: wav_other = weight_other @ av_other  [32,64] ----------------
    {
        const int o = tid & 63;
        const int g = tid >> 6;
        float a[8];
        #pragma unroll
        for (int r = 0; r < 8; r++) a[r] = 0.f;
        #pragma unroll 2
        for (int m = 0; m < MM; m++) {
            float av = sm.av_o[m][o];
            #pragma unroll
            for (int r = 0; r < 8; r++)
                a[r] = fmaf(sm.w_o[g * 8 + r][m], av, a[r]);
        }
        #pragma unroll
        for (int r = 0; r < 8; r++) sm.wav_o[g * 8 + r][o] = a[r];
    }
    __syncthreads();

    // ---------------- Phase H: u = [base|wav_o] @ W_f1,  v = delta @ W_f1[:64] ----------------
    {
        const int o = tid & 63;
        const int g = tid >> 6;
        float aU[8], aV[8];
        #pragma unroll
        for (int r = 0; r < 8; r++) { aU[r] = 0.f; aV[r] = 0.f; }
        #pragma unroll 2
        for (int k = 0; k < DAV_; k++) {
            float wf = W_f1[k * HID_ + o];
            #pragma unroll
            for (int r = 0; r < 8; r++) {
                aU[r] = fmaf(sm.base_[g * 8 + r][k], wf, aU[r]);
                aV[r] = fmaf(sm.delta[g * 8 + r][k], wf, aV[r]);
            }
        }
        #pragma unroll 2
        for (int k = 0; k < DAV_; k++) {
            float wf = W_f1[(DAV_ + k) * HID_ + o];
            #pragma unroll
            for (int r = 0; r < 8; r++)
                aU[r] = fmaf(sm.wav_o[g * 8 + r][k], wf, aU[r]);
        }
        #pragma unroll
        for (int r = 0; r < 8; r++) {
            sm.u[g * 8 + r][o] = aU[r];
            sm.v[g * 8 + r][o] = aV[r];
        }
    }
    __syncthreads();

    // ---------------- Phase I: value[i,j] = sum_f wf2[f]*lrelu(u[i,f] + w[i,j]*v[j,f]) ----------------
    for (int idx = tid; idx < NN * NN; idx += 256) {
        int i = idx >> 5, j = idx & 31;
        float wij = sm.w[i][j];
        float acc = 0.f;
        #pragma unroll 8
        for (int f = 0; f < HID_; f++) {
            float p = fmaf(wij, sm.v[j][f], sm.u[i][f]);
            float l = p > 0.f ? p : 0.01f * p;
            acc = fmaf(sm.wf2[f], l, acc);
        }
        out[OFF_VAL + b * NN * NN + i * NN + j] = acc;
    }
}

extern "C" void kernel_launch(void* const* d_in, const int* in_sizes, int n_in,
                              void* d_out, int out_size) {
    const float* states        = (const float*)d_in[0];
    const float* policies      = (const float*)d_in[1];
    const float* actions       = (const float*)d_in[2];
    const float* states_other  = (const float*)d_in[3];
    const float* actions_other = (const float*)d_in[4];
    const float* W_key         = (const float*)d_in[5];
    const float* W_query       = (const float*)d_in[6];
    const float* W_av          = (const float*)d_in[7];
    const float* W_key_other   = (const float*)d_in[8];
    const float* W_query_other = (const float*)d_in[9];
    const float* W_av_other    = (const float*)d_in[10];
    const float* W_f1          = (const float*)d_in[11];
    const float* W_f2          = (const float*)d_in[12];
    float* out = (float*)d_out;

    const int smem_bytes = (int)sizeof(Smem);   // ~182 KB
    cudaFuncSetAttribute(critic_dual_attn_kernel,
                         cudaFuncAttributeMaxDynamicSharedMemorySize, smem_bytes);

    critic_dual_attn_kernel<<<BB, 256, smem_bytes>>>(
        states, policies, actions, states_other, actions_other,
        W_key, W_query, W_av, W_key_other, W_query_other, W_av_other,
        W_f1, W_f2, out);
}